// round 2
// baseline (speedup 1.0000x reference)
#include <cuda_runtime.h>
#include <math.h>

#define BATCH   8
#define NPTS    8192
#define NPOINT  2048
#define NSAMPLE 32

// ---------------- scratch (no allocation allowed) ----------------
__device__ int   g_ball_idx[BATCH * NPOINT * NSAMPLE];
__device__ float g_fw1[64 * 68];
__device__ float g_fb1[64];
__device__ float g_fw2[64 * 64];
__device__ float g_fb2[64];
__device__ float g_fw3[128 * 64];
__device__ float g_fb3[128];

// ---------------- fold BN-affine into weights ----------------
__global__ void prep_kernel(const float* __restrict__ w1, const float* __restrict__ b1,
                            const float* __restrict__ g1, const float* __restrict__ bt1,
                            const float* __restrict__ w2, const float* __restrict__ b2,
                            const float* __restrict__ g2, const float* __restrict__ bt2,
                            const float* __restrict__ w3, const float* __restrict__ b3,
                            const float* __restrict__ g3, const float* __restrict__ bt3)
{
    int t = blockIdx.x * blockDim.x + threadIdx.x;
    int stride = gridDim.x * blockDim.x;
    const float inv = 1.0f / sqrtf(1.0f + 1e-5f);
    for (int i = t; i < 64 * 68; i += stride) {
        int o = i / 68, c = i % 68;
        g_fw1[i] = (c < 67) ? (g1[o] * inv) * w1[o * 67 + c] : 0.0f;
    }
    for (int i = t; i < 64 * 64; i += stride) {
        int o = i >> 6;
        g_fw2[i] = (g2[o] * inv) * w2[i];
    }
    for (int i = t; i < 128 * 64; i += stride) {
        int o = i >> 6;
        g_fw3[i] = (g3[o] * inv) * w3[i];
    }
    for (int i = t; i < 64; i += stride) {
        g_fb1[i] = (g1[i] * inv) * b1[i] + bt1[i];
        g_fb2[i] = (g2[i] * inv) * b2[i] + bt2[i];
    }
    for (int i = t; i < 128; i += stride)
        g_fb3[i] = (g3[i] * inv) * b3[i] + bt3[i];
}

// ---------------- farthest point sampling ----------------
// One 1024-thread block per batch. Points held in registers (8/thread) and in
// shared (for centroid broadcast). Distance math uses explicit rn mul/add in
// x,y,z order (matches XLA elemental emitter; NO fma contraction) so every
// pairwise distance is bitwise identical to the reference, making every
// argmax decision identical (tie-break = smallest index, like jnp.argmax).
__global__ void __launch_bounds__(1024, 1)
fps_kernel(const float* __restrict__ xyz, float* __restrict__ out_xyz)
{
    extern __shared__ float sm[];
    float* sx = sm;
    float* sy = sm + NPTS;
    float* sz = sm + 2 * NPTS;
    __shared__ float rv[32];
    __shared__ int   ri[32];
    __shared__ int   sfar;

    int b = blockIdx.x, tid = threadIdx.x;
    const float* xb = xyz + (size_t)b * NPTS * 3;

    float px[8], py[8], pz[8], dist[8];
#pragma unroll
    for (int k = 0; k < 8; k++) {
        int p = tid + k * 1024;
        float x = xb[3 * p], y = xb[3 * p + 1], z = xb[3 * p + 2];
        sx[p] = x; sy[p] = y; sz[p] = z;
        px[k] = x; py[k] = y; pz[k] = z;
        dist[k] = 1e10f;
    }
    __syncthreads();

    int far = 0;
    float* ob = out_xyz + (size_t)b * NPOINT * 3;

    for (int it = 0; it < NPOINT; it++) {
        float cx = sx[far], cy = sy[far], cz = sz[far];
        if (tid == 0) { ob[3 * it] = cx; ob[3 * it + 1] = cy; ob[3 * it + 2] = cz; }

        float bv = -1.0f; int bi = 0;
#pragma unroll
        for (int k = 0; k < 8; k++) {
            float dx = __fsub_rn(px[k], cx);
            float dy = __fsub_rn(py[k], cy);
            float dz = __fsub_rn(pz[k], cz);
            float d  = __fmul_rn(dx, dx);
            d = __fadd_rn(d, __fmul_rn(dy, dy));
            d = __fadd_rn(d, __fmul_rn(dz, dz));
            float nd = fminf(dist[k], d);
            dist[k] = nd;
            if (nd > bv) { bv = nd; bi = tid + k * 1024; }  // ascending index: strict > keeps first
        }
        // warp reduce (max value, tie -> min index)
#pragma unroll
        for (int off = 16; off > 0; off >>= 1) {
            float ov = __shfl_down_sync(0xffffffffu, bv, off);
            int   oi = __shfl_down_sync(0xffffffffu, bi, off);
            if (ov > bv || (ov == bv && oi < bi)) { bv = ov; bi = oi; }
        }
        int w = tid >> 5;
        if ((tid & 31) == 0) { rv[w] = bv; ri[w] = bi; }
        __syncthreads();
        if (w == 0) {
            bv = rv[tid & 31]; bi = ri[tid & 31];
#pragma unroll
            for (int off = 16; off > 0; off >>= 1) {
                float ov = __shfl_down_sync(0xffffffffu, bv, off);
                int   oi = __shfl_down_sync(0xffffffffu, bi, off);
                if (ov > bv || (ov == bv && oi < bi)) { bv = ov; bi = oi; }
            }
            if (tid == 0) sfar = bi;
        }
        __syncthreads();
        far = sfar;
    }
}

// ---------------- ball query ----------------
// Warp per centroid. Indices are naturally ascending, so "sort then take
// first NSAMPLE" == scan in order collecting first NSAMPLE hits. Early exit.
__global__ void __launch_bounds__(256)
ballq_kernel(const float* __restrict__ xyz, const float* __restrict__ cxyz)
{
    __shared__ int sidx[8][NSAMPLE];
    int warp = threadIdx.x >> 5, lane = threadIdx.x & 31;
    int g = blockIdx.x * 8 + warp;          // 0 .. BATCH*NPOINT-1
    int b = g >> 11;

    const float* cp = cxyz + (size_t)g * 3;
    float cx = cp[0], cy = cp[1], cz = cp[2];
    const float* xb = xyz + (size_t)b * NPTS * 3;
    const float r2 = (float)(0.2 * 0.2);    // matches JAX weak-typed python scalar
    unsigned ltmask = (1u << lane) - 1u;

    int count = 0;
    for (int base = 0; base < NPTS; base += 32) {
        int p = base + lane;
        float xv = xb[3 * p], yv = xb[3 * p + 1], zv = xb[3 * p + 2];
        float dx = __fsub_rn(cx, xv);
        float dy = __fsub_rn(cy, yv);
        float dz = __fsub_rn(cz, zv);
        float d  = __fmul_rn(dx, dx);
        d = __fadd_rn(d, __fmul_rn(dy, dy));
        d = __fadd_rn(d, __fmul_rn(dz, dz));
        int in = (d <= r2) ? 1 : 0;         // == !(d > r2), reference semantics
        unsigned m = __ballot_sync(0xffffffffu, in);
        if (in) {
            int pos = count + __popc(m & ltmask);
            if (pos < NSAMPLE) sidx[warp][pos] = p;
        }
        count += __popc(m);
        if (count >= NSAMPLE) break;        // warp-uniform
    }
    __syncwarp();
    int v = (lane < count) ? sidx[warp][lane] : sidx[warp][0];  // pad with first
    g_ball_idx[(size_t)g * NSAMPLE + lane] = v;
}

// ---------------- fused 3-layer MLP + max-pool ----------------
// 128 threads = 4 warps, warp per centroid, lane per sample.
// Folded weights staged in shared (float4 loads: 1 LDS.128 per 4 FFMA).
// x / y1 / y2 live fully in registers (full unroll), warp-shuffle max fused
// into layer 3 so y3 never needs 128 registers.
__global__ void __launch_bounds__(128, 3)
mlp_kernel(const float* __restrict__ xyz, const float* __restrict__ feats,
           const float* __restrict__ cxyz, float* __restrict__ out_feats)
{
    extern __shared__ float swm[];
    float* sw1 = swm;                 // 64*68
    float* sw2 = sw1 + 64 * 68;       // 64*64
    float* sw3 = sw2 + 64 * 64;       // 128*64
    float* sb1 = sw3 + 128 * 64;      // 64
    float* sb2 = sb1 + 64;            // 64
    float* sb3 = sb2 + 64;            // 128

    int tid = threadIdx.x;
    for (int i = tid; i < 64 * 68;  i += 128) sw1[i] = g_fw1[i];
    for (int i = tid; i < 64 * 64;  i += 128) sw2[i] = g_fw2[i];
    for (int i = tid; i < 128 * 64; i += 128) sw3[i] = g_fw3[i];
    if (tid < 64)  { sb1[tid] = g_fb1[tid]; sb2[tid] = g_fb2[tid]; }
    if (tid < 128)   sb3[tid] = g_fb3[tid];
    __syncthreads();

    int warp = tid >> 5, lane = tid & 31;
    int g = blockIdx.x * 4 + warp;
    int b = g >> 11, s = g & 2047;

    const float* cp = cxyz + (size_t)(b * NPOINT + s) * 3;
    float cx = cp[0], cy = cp[1], cz = cp[2];
    int idx = g_ball_idx[(size_t)g * NSAMPLE + lane];
    const float* pp = xyz + (size_t)(b * NPTS + idx) * 3;

    float x[68];
    x[0] = (pp[0] - cx) / 0.2f;
    x[1] = (pp[1] - cy) / 0.2f;
    x[2] = (pp[2] - cz) / 0.2f;
    const float4* pf = (const float4*)(feats + (size_t)(b * NPTS + idx) * 64);
#pragma unroll
    for (int q = 0; q < 16; q++) {
        float4 f = pf[q];
        x[3 + 4 * q] = f.x; x[4 + 4 * q] = f.y;
        x[5 + 4 * q] = f.z; x[6 + 4 * q] = f.w;
    }
    x[67] = 0.0f;

    float y1[64];
#pragma unroll
    for (int o = 0; o < 64; o++) {
        float acc = sb1[o];
        const float4* wv = (const float4*)(sw1 + o * 68);
#pragma unroll
        for (int q = 0; q < 17; q++) {
            float4 w = wv[q];
            acc = fmaf(w.x, x[4 * q + 0], acc);
            acc = fmaf(w.y, x[4 * q + 1], acc);
            acc = fmaf(w.z, x[4 * q + 2], acc);
            acc = fmaf(w.w, x[4 * q + 3], acc);
        }
        y1[o] = fmaxf(acc, 0.0f);
    }

    float y2[64];
#pragma unroll
    for (int o = 0; o < 64; o++) {
        float acc = sb2[o];
        const float4* wv = (const float4*)(sw2 + o * 64);
#pragma unroll
        for (int q = 0; q < 16; q++) {
            float4 w = wv[q];
            acc = fmaf(w.x, y1[4 * q + 0], acc);
            acc = fmaf(w.y, y1[4 * q + 1], acc);
            acc = fmaf(w.z, y1[4 * q + 2], acc);
            acc = fmaf(w.w, y1[4 * q + 3], acc);
        }
        y2[o] = fmaxf(acc, 0.0f);
    }

    float rr[4];
#pragma unroll
    for (int o = 0; o < 128; o++) {
        float acc = sb3[o];
        const float4* wv = (const float4*)(sw3 + o * 64);
#pragma unroll
        for (int q = 0; q < 16; q++) {
            float4 w = wv[q];
            acc = fmaf(w.x, y2[4 * q + 0], acc);
            acc = fmaf(w.y, y2[4 * q + 1], acc);
            acc = fmaf(w.z, y2[4 * q + 2], acc);
            acc = fmaf(w.w, y2[4 * q + 3], acc);
        }
        acc = fmaxf(acc, 0.0f);
        // max over the 32 samples (butterfly: every lane ends with the max)
#pragma unroll
        for (int off = 16; off > 0; off >>= 1)
            acc = fmaxf(acc, __shfl_xor_sync(0xffffffffu, acc, off));
        if (lane == (o & 31)) rr[o >> 5] = acc;
    }
    float* ob = out_feats + (size_t)(b * NPOINT + s) * 128;
#pragma unroll
    for (int j = 0; j < 4; j++) ob[j * 32 + lane] = rr[j];
}

// ---------------- launch ----------------
extern "C" void kernel_launch(void* const* d_in, const int* in_sizes, int n_in,
                              void* d_out, int out_size)
{
    const float* xyz   = (const float*)d_in[0];
    const float* feats = (const float*)d_in[1];

    float* out       = (float*)d_out;
    float* out_xyz   = out;                          // [B, NPOINT, 3]
    float* out_feats = out + BATCH * NPOINT * 3;     // [B, NPOINT, 128]

    cudaFuncSetAttribute(fps_kernel, cudaFuncAttributeMaxDynamicSharedMemorySize, 3 * NPTS * 4);
    cudaFuncSetAttribute(mlp_kernel, cudaFuncAttributeMaxDynamicSharedMemorySize, 67584);

    prep_kernel<<<32, 256>>>((const float*)d_in[2],  (const float*)d_in[3],
                             (const float*)d_in[4],  (const float*)d_in[5],
                             (const float*)d_in[6],  (const float*)d_in[7],
                             (const float*)d_in[8],  (const float*)d_in[9],
                             (const float*)d_in[10], (const float*)d_in[11],
                             (const float*)d_in[12], (const float*)d_in[13]);

    fps_kernel<<<BATCH, 1024, 3 * NPTS * 4>>>(xyz, out_xyz);

    ballq_kernel<<<(BATCH * NPOINT) / 8, 256>>>(xyz, out_xyz);

    mlp_kernel<<<(BATCH * NPOINT) / 4, 128, 67584>>>(xyz, feats, out_xyz, out_feats);
}